// round 11
// baseline (speedup 1.0000x reference)
#include <cuda_runtime.h>
#include <cuda_bf16.h>
#include <cstdint>

#define B_   8
#define H_   16
#define S_   1024
#define D_   64
#define BH_  (B_*H_)
#define NT   256
#define NCH  16            // 64-col chunks

#define OUT_O ((size_t)BH_*S_*D_)
#define OUT_W ((size_t)BH_*S_*S_)

// pre-swizzled bf16 hi/lo MMA-ready tiles: 16KB per (bh, chunk)
__device__ uint4 g_Kst[BH_*NCH*1024];   // K tile: [64 s][64 d]
__device__ uint4 g_Vst[BH_*NCH*1024];   // V tile: [64 d][64 s]

// ---- smem (from 1KB-aligned base) ----
#define OFF_E0   0u        // e-stage hi (16K, [128][64] bf16)
#define OFF_E1   16384u    // e-stage lo
#define OFF_KB   32768u    // K tile buf (hi 8K + lo 8K)
#define OFF_VB   49152u    // V tile buf (hi 8K + lo 8K)
#define OFF_DT   65536u    // D transpose: 128 x 65 f32 = 33280
#define OFF_MISC 98816u
#define OFF_TM    (OFF_MISC + 0u)
#define OFF_KBAR  (OFF_MISC + 8u)
#define OFF_VBAR  (OFF_MISC + 16u)
#define OFF_M1    (OFF_MISC + 24u)
#define OFF_M2    (OFF_MISC + 32u)
#define OFF_CONS  (OFF_MISC + 40u)
#define OFF_LS    (OFF_MISC + 64u)   // float[128]
#define SMEM_BYTES (OFF_MISC + 64u + 512u + 1024u)

#define IDESC_BF16_N64 ((1u<<4)|(1u<<7)|(1u<<10)|(8u<<17)|(8u<<24))
#define SWZ(o) ((o) ^ (((o) >> 3) & 0x70u))

#if defined(__CUDA_ARCH_FEAT_SM103_ALL) || defined(__CUDA_ARCH_FEAT_SM100_ALL)
#define HAS_TC 1
#endif

__device__ __forceinline__ uint32_t smem_u32(const void* p) {
    uint32_t a;
    asm("{ .reg .u64 t; cvta.to.shared.u64 t, %1; cvt.u32.u64 %0, t; }" : "=r"(a) : "l"(p));
    return a;
}
#define MBAR_INIT(a, n) asm volatile("mbarrier.init.shared.b64 [%0], %1;" :: "r"(a), "r"(n) : "memory")
#define MBAR_ARRIVE(a)  asm volatile("mbarrier.arrive.shared.b64 _, [%0];" :: "r"(a) : "memory")
#define MBAR_EXPECT(a, b) asm volatile("mbarrier.arrive.expect_tx.shared.b64 _, [%0], %1;" :: "r"(a), "r"(b) : "memory")
#define MBAR_WAIT(a, ph) do { \
    uint32_t _m = (a), _p = (ph), _d; \
    asm volatile("{ .reg .pred p; mbarrier.try_wait.parity.acquire.cta.shared::cta.b64 p, [%1], %2; selp.b32 %0,1,0,p; }" \
        : "=r"(_d) : "r"(_m), "r"(_p) : "memory"); \
    if (!_d) { \
        asm volatile("{ .reg .pred P1;\nWL_%=:\n mbarrier.try_wait.parity.acquire.cta.shared::cta.b64 P1, [%0], %1, 0x989680;\n @P1 bra.uni WD_%=;\n bra.uni WL_%=;\nWD_%=:\n}" \
            :: "r"(_m), "r"(_p) : "memory"); \
    } } while (0)
#define FENCE_ASYNC() asm volatile("fence.proxy.async.shared::cta;" ::: "memory")
#define BULK_G2S(dst, src, bytes, bar) \
    asm volatile("cp.async.bulk.shared::cluster.global.mbarrier::complete_tx::bytes [%0], [%1], %2, [%3];" \
        :: "r"(dst), "l"(src), "r"(bytes), "r"(bar) : "memory")

#ifdef HAS_TC
#define TC_ALLOC(a, n) asm volatile("tcgen05.alloc.cta_group::1.sync.aligned.shared::cta.b32 [%0], %1;" :: "r"(a), "r"(n) : "memory")
#define TC_RELINQ()    asm volatile("tcgen05.relinquish_alloc_permit.cta_group::1.sync.aligned;")
#define TC_DEALLOC(t, n) asm volatile("tcgen05.dealloc.cta_group::1.sync.aligned.b32 %0, %1;" :: "r"(t), "r"(n))
#define TC_COMMIT(bar) asm volatile("tcgen05.commit.cta_group::1.mbarrier::arrive::one.shared::cluster.b64 [%0];" :: "r"(bar) : "memory")
#define TC_WAIT_LD() asm volatile("tcgen05.wait::ld.sync.aligned;" ::: "memory")
#define TC_WAIT_ST() asm volatile("tcgen05.wait::st.sync.aligned;" ::: "memory")
#define TC_FENCE_BEFORE() asm volatile("tcgen05.fence::before_thread_sync;" ::: "memory")
#define TC_FENCE_AFTER()  asm volatile("tcgen05.fence::after_thread_sync;" ::: "memory")
#define TC_LD_X32(r, addr) \
    asm volatile("tcgen05.ld.sync.aligned.32x32b.x32.b32 " \
        "{%0,%1,%2,%3,%4,%5,%6,%7,%8,%9,%10,%11,%12,%13,%14,%15," \
        "%16,%17,%18,%19,%20,%21,%22,%23,%24,%25,%26,%27,%28,%29,%30,%31}, [%32];" \
        : "=r"((r)[0]),"=r"((r)[1]),"=r"((r)[2]),"=r"((r)[3]),"=r"((r)[4]),"=r"((r)[5]),"=r"((r)[6]),"=r"((r)[7]), \
          "=r"((r)[8]),"=r"((r)[9]),"=r"((r)[10]),"=r"((r)[11]),"=r"((r)[12]),"=r"((r)[13]),"=r"((r)[14]),"=r"((r)[15]), \
          "=r"((r)[16]),"=r"((r)[17]),"=r"((r)[18]),"=r"((r)[19]),"=r"((r)[20]),"=r"((r)[21]),"=r"((r)[22]),"=r"((r)[23]), \
          "=r"((r)[24]),"=r"((r)[25]),"=r"((r)[26]),"=r"((r)[27]),"=r"((r)[28]),"=r"((r)[29]),"=r"((r)[30]),"=r"((r)[31]) \
        : "r"(addr))
#define TC_ST_X32(addr, rg) \
    asm volatile("tcgen05.st.sync.aligned.32x32b.x32.b32 [%0], " \
        "{%1,%2,%3,%4,%5,%6,%7,%8,%9,%10,%11,%12,%13,%14,%15,%16," \
        "%17,%18,%19,%20,%21,%22,%23,%24,%25,%26,%27,%28,%29,%30,%31,%32};" \
        :: "r"(addr), \
           "r"((rg)[0]),"r"((rg)[1]),"r"((rg)[2]),"r"((rg)[3]),"r"((rg)[4]),"r"((rg)[5]),"r"((rg)[6]),"r"((rg)[7]), \
           "r"((rg)[8]),"r"((rg)[9]),"r"((rg)[10]),"r"((rg)[11]),"r"((rg)[12]),"r"((rg)[13]),"r"((rg)[14]),"r"((rg)[15]), \
           "r"((rg)[16]),"r"((rg)[17]),"r"((rg)[18]),"r"((rg)[19]),"r"((rg)[20]),"r"((rg)[21]),"r"((rg)[22]),"r"((rg)[23]), \
           "r"((rg)[24]),"r"((rg)[25]),"r"((rg)[26]),"r"((rg)[27]),"r"((rg)[28]),"r"((rg)[29]),"r"((rg)[30]),"r"((rg)[31]) \
        : "memory")

__device__ __forceinline__ void mma_bf16_ss(uint32_t d, uint64_t a, uint64_t b, uint32_t en) {
    asm volatile("{\n\t.reg .pred p;\n\tsetp.ne.u32 p, %4, 0;\n\t"
                 "tcgen05.mma.cta_group::1.kind::f16 [%0], %1, %2, %3, {%5,%5,%5,%5}, p;\n\t}"
                 :: "r"(d), "l"(a), "l"(b), "r"(IDESC_BF16_N64), "r"(en), "r"(0u) : "memory");
}
__device__ __forceinline__ void mma_bf16_ts(uint32_t d, uint32_t a, uint64_t b, uint32_t en) {
    asm volatile("{\n\t.reg .pred p;\n\tsetp.ne.u32 p, %4, 0;\n\t"
                 "tcgen05.mma.cta_group::1.kind::f16 [%0], [%1], %2, %3, {%5,%5,%5,%5}, p;\n\t}"
                 :: "r"(d), "r"(a), "l"(b), "r"(IDESC_BF16_N64), "r"(en), "r"(0u) : "memory");
}
#endif

static __device__ __forceinline__ uint64_t mk_desc(uint32_t addr) {
    return (uint64_t(2) << 61) | (uint64_t(1) << 46) | (uint64_t(64) << 32) | (uint64_t(1) << 16)
         | ((uint64_t)(addr >> 4) & 0x3FFFull);
}

__device__ __forceinline__ void cvt2(float x, float y, uint32_t& hw, uint32_t& lw) {
    __nv_bfloat162 h = __floats2bfloat162_rn(x, y);
    float hx = __bfloat162float(h.x), hy = __bfloat162float(h.y);
    __nv_bfloat162 l = __floats2bfloat162_rn(x - hx, y - hy);
    hw = *(uint32_t*)&h;
    lw = *(uint32_t*)&l;
}
__device__ __forceinline__ void stage4(float4 f, char* p0, char* p1, uint32_t off) {
    uint32_t h0, l0, h1, l1;
    cvt2(f.x, f.y, h0, l0);
    cvt2(f.z, f.w, h1, l1);
    uint32_t so = SWZ(off);
    *(uint2*)(p0 + so) = make_uint2(h0, h1);
    *(uint2*)(p1 + so) = make_uint2(l0, l1);
}

// ===================== pre-pass: K/V -> swizzled bf16 hi/lo tiles =====================
__global__ void prep_kv(const float* __restrict__ k, const float* __restrict__ v) {
    __shared__ uint8_t tile[16384];
    const int c = blockIdx.x, which = blockIdx.y, bh = blockIdx.z;
    const int tid = threadIdx.x;
    if (which == 0) {
        const float4* k4 = (const float4*)(k + (size_t)bh * D_ * S_);
        for (int i = tid; i < 1024; i += 256) {
            int d = i >> 4, sq = i & 15;
            float4 f = k4[d * (S_/4) + c * 16 + sq];
            float vals[4] = {f.x, f.y, f.z, f.w};
            #pragma unroll
            for (int e = 0; e < 4; e++) {
                int s = sq * 4 + e;
                uint32_t off = SWZ((uint32_t)(s * 128 + d * 2));
                __nv_bfloat16 h = __float2bfloat16(vals[e]);
                __nv_bfloat16 l = __float2bfloat16(vals[e] - __bfloat162float(h));
                *(uint16_t*)(tile + off)        = *(uint16_t*)&h;
                *(uint16_t*)(tile + 8192 + off) = *(uint16_t*)&l;
            }
        }
        __syncthreads();
        uint4* dst = g_Kst + ((size_t)bh * NCH + c) * 1024;
        const uint4* t4 = (const uint4*)tile;
        for (int i = tid; i < 1024; i += 256) dst[i] = t4[i];
    } else {
        const float4* v4 = (const float4*)(v + (size_t)bh * S_ * D_);
        for (int i = tid; i < 1024; i += 256) {
            int s = i >> 4, dq = i & 15;
            float4 f = v4[(c * 64 + s) * (D_/4) + dq];
            float vals[4] = {f.x, f.y, f.z, f.w};
            #pragma unroll
            for (int e = 0; e < 4; e++) {
                int d = dq * 4 + e;
                uint32_t off = SWZ((uint32_t)(d * 128 + s * 2));
                __nv_bfloat16 h = __float2bfloat16(vals[e]);
                __nv_bfloat16 l = __float2bfloat16(vals[e] - __bfloat162float(h));
                *(uint16_t*)(tile + off)        = *(uint16_t*)&h;
                *(uint16_t*)(tile + 8192 + off) = *(uint16_t*)&l;
            }
        }
        __syncthreads();
        uint4* dst = g_Vst + ((size_t)bh * NCH + c) * 1024;
        const uint4* t4 = (const uint4*)tile;
        for (int i = tid; i < 1024; i += 256) dst[i] = t4[i];
    }
}

// ===================== main fused attention =====================
__global__ void __launch_bounds__(NT, 2)
attn_main(const float* __restrict__ q, const float* __restrict__ prev,
          const float* __restrict__ mask, const float* __restrict__ scale_p,
          float* __restrict__ out)
{
#ifdef HAS_TC
    extern __shared__ char smraw[];
    const uint32_t sb0 = smem_u32(smraw);
    const uint32_t sbase = (sb0 + 1023u) & ~1023u;
    char* sm = smraw + (sbase - sb0);

    const int tid = threadIdx.x;
    const int wid = tid >> 5;
    const int wg  = wid >> 2;
    const int r   = ((wid & 3) << 5) | (tid & 31);
    const int half = (tid & 31) >> 4;
    const int cl   = tid & 15;
    const int bh  = blockIdx.x >> 3;
    const int qb  = (blockIdx.x & 7) * 128;
    const float scale = *scale_p;

    float* outO = out;
    float* outW = out + OUT_O;
    float* outS = outW + OUT_W;
    float* lsum = (float*)(sm + OFF_LS);
    float* dt   = (float*)(sm + OFF_DT);

    const float4* qp4 = (const float4*)(q + ((size_t)bh * S_ + qb) * D_);
    const char* kst = (const char*)(g_Kst + (size_t)bh * NCH * 1024);
    const char* vst = (const char*)(g_Vst + (size_t)bh * NCH * 1024);

    if (tid == 0) {
        MBAR_INIT(sbase + OFF_KBAR, 1);
        MBAR_INIT(sbase + OFF_VBAR, 1);
        MBAR_INIT(sbase + OFF_M1, 1);
        MBAR_INIT(sbase + OFF_M2, 1);
        MBAR_INIT(sbase + OFF_CONS, NT);
    }
    if (tid < 128) lsum[tid] = 0.0f;
    if (wid == 0) { TC_ALLOC(sbase + OFF_TM, 256); TC_RELINQ(); }
    __syncthreads();
    uint32_t tmem;
    asm volatile("ld.shared.b32 %0, [%1];" : "=r"(tmem) : "r"(sbase + OFF_TM));
    const uint32_t TM_D = tmem;          // 64 cols
    const uint32_t TM_O = tmem + 64;     // 64 cols
    const uint32_t TM_Q = tmem + 128;    // hi 32 + lo 32 ... 64 cols (wait: 32+32)

    // ---- Q -> TMEM (warps 0-3; thread tid holds row tid) ----
    if (tid < 128) {
        uint32_t hi[32], lo[32];
        const float4* qrow = qp4 + tid * 16;
        #pragma unroll
        for (int j = 0; j < 16; j++) {
            float4 f = qrow[j];
            cvt2(f.x, f.y, hi[2*j],   lo[2*j]);
            cvt2(f.z, f.w, hi[2*j+1], lo[2*j+1]);
        }
        uint32_t woff = (uint32_t)(tid >> 5) << 21;
        TC_ST_X32(TM_Q + woff, hi);
        TC_ST_X32(TM_Q + 32 + woff, lo);
        TC_WAIT_ST();
    }
    TC_FENCE_BEFORE();
    __syncthreads();

    // prologue: K(0) bulk copy
    if (tid == 0) {
        MBAR_EXPECT(sbase + OFF_KBAR, 16384);
        BULK_G2S(sbase + OFF_KB, kst, 16384, sbase + OFF_KBAR);
    }

    int phK = 0, phV = 0, phM1 = 0, phM2 = 0, phC = 0;
    uint64_t EA0 = mk_desc(sbase + OFF_E0), EA1 = mk_desc(sbase + OFF_E1);
    uint64_t KB0 = mk_desc(sbase + OFF_KB), KB1 = mk_desc(sbase + OFF_KB + 8192u);
    uint64_t VB0 = mk_desc(sbase + OFF_VB), VB1 = mk_desc(sbase + OFF_VB + 8192u);

    for (int c = 0; c <= NCH; c++) {
        // ---------- epilogue of chunk cc = c-1 ----------
        if (c >= 1) {
            const int cc = c - 1;
            const size_t colb = (size_t)cc * 64 + cl * 4;
            float4 pv[8];
            #pragma unroll
            for (int j = 0; j < 8; j++) {
                int rr = wid * 16 + 2 * j + half;
                pv[j] = *(const float4*)(prev + ((size_t)bh * S_ + qb + rr) * S_ + colb);
            }
            MBAR_WAIT(sbase + OFF_M1, phM1); phM1 ^= 1;
            if (tid == 0 && cc + 1 < NCH) {            // KB free: refill K(cc+1)
                MBAR_EXPECT(sbase + OFF_KBAR, 16384);
                BULK_G2S(sbase + OFF_KB, kst + (size_t)(cc + 1) * 16384, 16384, sbase + OFF_KBAR);
            }
            TC_FENCE_AFTER();
            uint32_t dr[32];
            TC_LD_X32(dr, TM_D + (uint32_t)wg * 32u);
            TC_WAIT_LD();
            TC_FENCE_BEFORE();
            MBAR_ARRIVE(sbase + OFF_CONS);
            if (cc >= 1) { MBAR_WAIT(sbase + OFF_M2, phM2); phM2 ^= 1; }  // ES + VB free
            if (tid == 0) {                             // VB free: load V(cc)
                MBAR_EXPECT(sbase + OFF_VBAR, 16384);
                BULK_G2S(sbase + OFF_VB, vst + (size_t)cc * 16384, 16384, sbase + OFF_VBAR);
            }
            #pragma unroll
            for (int i = 0; i < 32; i++)
                dt[r * 65 + wg * 32 + i] = __uint_as_float(dr[i]);
            __syncthreads();
            #pragma unroll
            for (int j = 0; j < 8; j++) {
                int rr = wid * 16 + 2 * j + half;
                size_t gr = (size_t)bh * S_ + qb + rr;
                float4 mk = *(const float4*)(mask + (size_t)(qb + rr) * S_ + colb);
                int db = rr * 65 + cl * 4;
                float4 s;
                s.x = dt[db + 0] * mk.x * scale + pv[j].x;
                s.y = dt[db + 1] * mk.y * scale + pv[j].y;
                s.z = dt[db + 2] * mk.z * scale + pv[j].z;
                s.w = dt[db + 3] * mk.w * scale + pv[j].w;
                *(float4*)(outS + gr * S_ + colb) = s;
                float4 e;
                e.x = __expf(s.x); e.y = __expf(s.y);
                e.z = __expf(s.z); e.w = __expf(s.w);
                stage4(e, sm + OFF_E0, sm + OFF_E1, (uint32_t)rr * 128u + (uint32_t)cl * 8u);
                float val = e.x + e.y + e.z + e.w;
                val += __shfl_xor_sync(0xffffffffu, val, 1);
                val += __shfl_xor_sync(0xffffffffu, val, 2);
                val += __shfl_xor_sync(0xffffffffu, val, 4);
                val += __shfl_xor_sync(0xffffffffu, val, 8);
                if (cl == 0) lsum[rr] += val;
            }
            FENCE_ASYNC();
            __syncthreads();
            if (tid == 0) {
                MBAR_WAIT(sbase + OFF_VBAR, phV); phV ^= 1;   // V(cc) arrived
                #pragma unroll
                for (int t = 0; t < 4; t++) mma_bf16_ss(TM_O, EA0 + t*2, VB0 + t*2, (cc > 0 || t > 0) ? 1u : 0u);
                #pragma unroll
                for (int t = 0; t < 4; t++) mma_bf16_ss(TM_O, EA0 + t*2, VB1 + t*2, 1u);
                #pragma unroll
                for (int t = 0; t < 4; t++) mma_bf16_ss(TM_O, EA1 + t*2, VB0 + t*2, 1u);
                TC_COMMIT(sbase + OFF_M2);
            }
        }
        // ---------- issue MMA1(c) ----------
        if (c < NCH && tid == 0) {
            MBAR_WAIT(sbase + OFF_KBAR, phK); phK ^= 1;       // K(c) arrived
            if (c >= 1) { MBAR_WAIT(sbase + OFF_CONS, phC); phC ^= 1; }  // D consumed
            #pragma unroll
            for (int t = 0; t < 4; t++) mma_bf16_ts(TM_D, TM_Q + t*8,      KB0 + t*2, (t > 0) ? 1u : 0u);
            #pragma unroll
            for (int t = 0; t < 4; t++) mma_bf16_ts(TM_D, TM_Q + t*8,      KB1 + t*2, 1u);
            #pragma unroll
            for (int t = 0; t < 4; t++) mma_bf16_ts(TM_D, TM_Q + 32 + t*8, KB0 + t*2, 1u);
            TC_COMMIT(sbase + OFF_M1);
        }
    }

    // ---------- finalize l, write O ----------
    MBAR_WAIT(sbase + OFF_M2, phM2);            // MMA2(15) done
    TC_FENCE_AFTER();
    __syncthreads();
    if (tid < 128) lsum[tid] = 1.0f / lsum[tid];
    __syncthreads();
    {
        uint32_t o[32];
        TC_LD_X32(o, TM_O + (uint32_t)wg * 32u);
        TC_WAIT_LD();
        float inv = lsum[r];
        float4* oo = (float4*)(outO + ((size_t)bh * S_ + qb + r) * D_ + wg * 32);
        #pragma unroll
        for (int j = 0; j < 8; j++)
            oo[j] = make_float4(__uint_as_float(o[4*j]) * inv, __uint_as_float(o[4*j+1]) * inv,
                                __uint_as_float(o[4*j+2]) * inv, __uint_as_float(o[4*j+3]) * inv);
    }
    TC_FENCE_BEFORE();
    __syncthreads();
    if (wid == 0) TC_DEALLOC(tmem, 256);

    // ---------- Phase B: pure streaming W = exp(S) * inv_l ----------
    {
        const float4* Sblk = (const float4*)(outS + (size_t)(bh * S_ + qb) * S_);
        float4*       Wblk = (float4*)      (outW + (size_t)(bh * S_ + qb) * S_);
        #pragma unroll 4
        for (int i = tid; i < 128 * (S_/4); i += NT) {
            int row = i >> 8;                   // 256 float4 per row
            float il = lsum[row];
            float4 s = Sblk[i];
            float4 w;
            w.x = __expf(s.x) * il;
            w.y = __expf(s.y) * il;
            w.z = __expf(s.z) * il;
            w.w = __expf(s.w) * il;
            Wblk[i] = w;
        }
    }
#endif  // HAS_TC
}

extern "C" void kernel_launch(void* const* d_in, const int* in_sizes, int n_in,
                              void* d_out, int out_size)
{
    const float* q     = (const float*)d_in[0];
    const float* k     = (const float*)d_in[1];
    const float* v     = (const float*)d_in[2];
    const float* prev  = (const float*)d_in[3];
    const float* mask  = (const float*)d_in[4];
    const float* scale = (const float*)d_in[5];
    float* out = (float*)d_out;

    dim3 pg(NCH, 2, BH_);
    prep_kv<<<pg, 256>>>(k, v);

    cudaFuncSetAttribute(attn_main, cudaFuncAttributeMaxDynamicSharedMemorySize, SMEM_BYTES);
    attn_main<<<BH_ * 8, NT, SMEM_BYTES>>>(q, prev, mask, scale, out);
}